// round 1
// baseline (speedup 1.0000x reference)
#include <cuda_runtime.h>
#include <math.h>
#include <stdint.h>

#define Nn 4096
#define Hh 4
#define NWORDS 128   // Nn/32

// ---------------- scratch (static device globals; no allocation) -------------
__device__ uint32_t g_mask[Nn * NWORDS];          // 2 MB packed adjacency
__device__ float g_Wh[Hh * Nn * 64];              // 4 MB, reused per stage (max O=64)
__device__ float g_f1[Hh * Nn];
__device__ float g_f2[Hh * Nn];
__device__ float g_E1p[Hh * Nn];
__device__ float g_E1n[Hh * Nn];
__device__ float g_E2p[Hh * Nn];
__device__ float g_E2n[Hh * Nn];
__device__ float g_h1[Nn * 256];
__device__ float g_h2[Nn * 128];
__device__ float g_h3[Nn * 64];

// ---------------- pack adjacency into bitmask --------------------------------
__global__ void pack_mask_kernel(const int* __restrict__ adj) {
    int idx = blockIdx.x * blockDim.x + threadIdx.x;  // one thread per 32-bit word
    int i = idx >> 7;
    int w = idx & 127;
    const int4* p = reinterpret_cast<const int4*>(adj + (size_t)i * Nn + (w << 5));
    uint32_t m = 0u;
#pragma unroll
    for (int q = 0; q < 8; q++) {
        int4 v = p[q];
        if (v.x) m |= 1u << (q * 4 + 0);
        if (v.y) m |= 1u << (q * 4 + 1);
        if (v.z) m |= 1u << (q * 4 + 2);
        if (v.w) m |= 1u << (q * 4 + 3);
    }
    g_mask[idx] = m;
}

// ---------------- Wh = x @ W[h]  (per head) ----------------------------------
// CTA tile: 128 rows x O cols, 256 threads, microtile TM x TN.
template <int FIN, int O, int TM, int TN>
__global__ __launch_bounds__(256) void gemm_wh_kernel(const float* __restrict__ x,
                                                      const float* __restrict__ W) {
    const int h = blockIdx.y;
    const int n0 = blockIdx.x * 128;
    const int t = threadIdx.x;
    __shared__ float xs[32][132];  // [f][row], padded, 16B-aligned rows
    __shared__ float ws[32][O];    // [f][o]
    const int CG = O / TN;
    const int rg = t / CG, cg = t % CG;
    float acc[TM][TN];
#pragma unroll
    for (int k = 0; k < TM; k++)
#pragma unroll
        for (int u = 0; u < TN; u++) acc[k][u] = 0.f;
    const float* Wc = W + (size_t)h * FIN * O;
    for (int f0 = 0; f0 < FIN; f0 += 32) {
        __syncthreads();
#pragma unroll
        for (int k = 0; k < 16; k++) {
            int idx = t + k * 256;
            int f = idx & 31, row = idx >> 5;
            xs[f][row] = x[(size_t)(n0 + row) * FIN + f0 + f];
        }
#pragma unroll
        for (int k = 0; k < (32 * O) / 256; k++) {
            int idx = t + k * 256;
            int o = idx % O, f = idx / O;
            ws[f][o] = Wc[(size_t)(f0 + f) * O + o];
        }
        __syncthreads();
#pragma unroll 8
        for (int f = 0; f < 32; f++) {
            float xv[TM], wv[TN];
#pragma unroll
            for (int q = 0; q < TM / 4; q++)
                *(float4*)&xv[q * 4] = *(const float4*)&xs[f][rg * TM + q * 4];
            if (TN >= 4) {
#pragma unroll
                for (int q = 0; q < TN / 4; q++)
                    *(float4*)&wv[q * 4] = *(const float4*)&ws[f][cg * TN + q * 4];
            } else {
                *(float2*)&wv[0] = *(const float2*)&ws[f][cg * TN];
            }
#pragma unroll
            for (int k = 0; k < TM; k++)
#pragma unroll
                for (int u = 0; u < TN; u++) acc[k][u] += xv[k] * wv[u];
        }
    }
#pragma unroll
    for (int k = 0; k < TM; k++) {
        int n = n0 + rg * TM + k;
#pragma unroll
        for (int u = 0; u < TN; u++)
            g_Wh[((size_t)h * Nn + n) * O + cg * TN + u] = acc[k][u];
    }
}

// ---------------- per-node attention scalars ---------------------------------
// f1 = Wh . a[:O], f2 = Wh . a[O:], plus exp factorization terms.
template <int O>
__global__ void fe_kernel(const float* __restrict__ a) {
    int idx = blockIdx.x * 256 + threadIdx.x;  // over Hh*Nn
    int h = idx >> 12;                          // / Nn
    const float* wr = g_Wh + (size_t)idx * O;
    const float* av = a + h * 2 * O;
    float f1 = 0.f, f2 = 0.f;
#pragma unroll
    for (int o = 0; o < O; o++) {
        float w = wr[o];
        f1 += w * av[o];
        f2 += w * av[O + o];
    }
    g_f1[idx] = f1;
    g_f2[idx] = f2;
    g_E1p[idx] = expf(f1);
    g_E1n[idx] = expf(0.2f * f1);
    g_E2p[idx] = expf(f2);
    g_E2n[idx] = expf(0.2f * f2);
}

// ---------------- masked-softmax aggregation + ELU + head concat -------------
// CTA: (head h, 128 rows), loops all 4096 j in chunks of 32.
// w_ij = mask ? exp(leaky(f1_i+f2_j)) : 0 built via precomputed exp factors;
// out_i = elu( (sum_j w_ij * Wh_j) / (sum_j w_ij) ).
template <int O, int TM, int TN>
__global__ __launch_bounds__(256) void agg_kernel(float* __restrict__ out, int HO) {
    const int h = blockIdx.y;
    const int n0 = blockIdx.x * 128;
    const int t = threadIdx.x;
    __shared__ float sWT[32][136];  // [jj][row], padded (544B rows, 16B aligned)
    __shared__ float sWh[32][O];    // [jj][o]
    __shared__ float sZ[128];
    __shared__ float sZpart[256];
    const int row = t & 127, half = t >> 7;  // weight-compute mapping
    const int base = h * Nn + n0 + row;
    const float f1v = g_f1[base];
    const float e1p = g_E1p[base];
    const float e1n = g_E1n[base];
    const int CG = O / TN;
    const int rg = t / CG, cg = t % CG;      // consume mapping
    float acc[TM][TN];
#pragma unroll
    for (int k = 0; k < TM; k++)
#pragma unroll
        for (int u = 0; u < TN; u++) acc[k][u] = 0.f;
    float zloc = 0.f;
    const float* WhH = g_Wh + (size_t)h * Nn * O;
    const float* f2H = g_f2 + h * Nn;
    const float* e2pH = g_E2p + h * Nn;
    const float* e2nH = g_E2n + h * Nn;
    const uint32_t* mrow = g_mask + (size_t)(n0 + row) * NWORDS;

    for (int c = 0; c < NWORDS; c++) {
        const int j0 = c << 5;
        __syncthreads();  // protect sWT/sWh reuse from previous chunk
        // stage Wh chunk
#pragma unroll
        for (int k = 0; k < (32 * O) / 256; k++) {
            int idx = t + k * 256;
            int o = idx % O, jj = idx / O;
            sWh[jj][o] = WhH[(size_t)(j0 + jj) * O + o];
        }
        // compute attention weights for this (row, 16-j half)
        uint32_t m = mrow[c] >> (half * 16);
#pragma unroll
        for (int b = 0; b < 16; b++) {
            int jj = (half << 4) + b;
            float s = f1v + f2H[j0 + jj];  // uniform across warp -> L1 broadcast
            float w = 0.f;
            if ((m >> b) & 1u)
                w = (s > 0.f) ? e1p * e2pH[j0 + jj] : e1n * e2nH[j0 + jj];
            sWT[jj][row] = w;
            zloc += w;
        }
        __syncthreads();
        // consume: acc += w * Wh
#pragma unroll 16
        for (int jj = 0; jj < 32; jj++) {
            float wv[TM], bv[TN];
#pragma unroll
            for (int q = 0; q < TM / 4; q++)
                *(float4*)&wv[q * 4] = *(const float4*)&sWT[jj][rg * TM + q * 4];
            if (TN >= 4) {
#pragma unroll
                for (int q = 0; q < TN / 4; q++)
                    *(float4*)&bv[q * 4] = *(const float4*)&sWh[jj][cg * TN + q * 4];
            } else {
                *(float2*)&bv[0] = *(const float2*)&sWh[jj][cg * TN];
            }
#pragma unroll
            for (int k = 0; k < TM; k++)
#pragma unroll
                for (int u = 0; u < TN; u++) acc[k][u] += wv[k] * bv[u];
        }
    }
    sZpart[t] = zloc;
    __syncthreads();
    if (t < 128) sZ[t] = sZpart[t] + sZpart[t + 128];
    __syncthreads();
#pragma unroll
    for (int k = 0; k < TM; k++) {
        int r = rg * TM + k;
        float inv = 1.f / sZ[r];
#pragma unroll
        for (int u = 0; u < TN; u++) {
            float v = acc[k][u] * inv;
            v = v > 0.f ? v : expm1f(v);  // elu
            out[(size_t)(n0 + r) * HO + h * O + cg * TN + u] = v;
        }
    }
}

// ---------------- final linear + log_softmax ---------------------------------
__global__ void final_kernel(const float* __restrict__ Wlin,
                             const float* __restrict__ blin,
                             float* __restrict__ out) {
    int lane = threadIdx.x & 31;
    int n = (blockIdx.x * blockDim.x + threadIdx.x) >> 5;  // one warp per row
    const float* hr = g_h3 + (size_t)n * 64;
    float v1 = -INFINITY;
    float a0 = blin[lane];
    float a1v = (lane < 8) ? blin[lane + 32] : 0.f;
#pragma unroll 16
    for (int k = 0; k < 64; k++) {
        float hv = hr[k];
        a0 += hv * Wlin[k * 40 + lane];
        if (lane < 8) a1v += hv * Wlin[k * 40 + lane + 32];
    }
    float v0 = a0;
    if (lane < 8) v1 = a1v;
    float m = fmaxf(v0, v1);
#pragma unroll
    for (int off = 16; off; off >>= 1) m = fmaxf(m, __shfl_xor_sync(0xffffffffu, m, off));
    float e = expf(v0 - m) + ((lane < 8) ? expf(v1 - m) : 0.f);
#pragma unroll
    for (int off = 16; off; off >>= 1) e += __shfl_xor_sync(0xffffffffu, e, off);
    float lse = m + logf(e);
    out[(size_t)n * 40 + lane] = v0 - lse;
    if (lane < 8) out[(size_t)n * 40 + lane + 32] = v1 - lse;
}

// ---------------- launch -----------------------------------------------------
extern "C" void kernel_launch(void* const* d_in, const int* in_sizes, int n_in,
                              void* d_out, int out_size) {
    const float* x    = (const float*)d_in[0];
    const int*   adj  = (const int*)d_in[1];
    const float* W1   = (const float*)d_in[2];
    const float* a1   = (const float*)d_in[3];
    const float* W2   = (const float*)d_in[4];
    const float* a2   = (const float*)d_in[5];
    const float* W3   = (const float*)d_in[6];
    const float* a3   = (const float*)d_in[7];
    const float* Wlin = (const float*)d_in[8];
    const float* blin = (const float*)d_in[9];
    float* out = (float*)d_out;

    float *h1, *h2, *h3;
    cudaGetSymbolAddress((void**)&h1, g_h1);
    cudaGetSymbolAddress((void**)&h2, g_h2);
    cudaGetSymbolAddress((void**)&h3, g_h3);

    pack_mask_kernel<<<(Nn * NWORDS) / 256, 256>>>(adj);

    dim3 grid(Nn / 128, Hh);

    // stage 1: Fin=512, O=64
    gemm_wh_kernel<512, 64, 8, 4><<<grid, 256>>>(x, W1);
    fe_kernel<64><<<(Hh * Nn) / 256, 256>>>(a1);
    agg_kernel<64, 8, 4><<<grid, 256>>>(h1, 256);

    // stage 2: Fin=256, O=32
    gemm_wh_kernel<256, 32, 4, 4><<<grid, 256>>>(h1, W2);
    fe_kernel<32><<<(Hh * Nn) / 256, 256>>>(a2);
    agg_kernel<32, 4, 4><<<grid, 256>>>(h2, 128);

    // stage 3: Fin=128, O=16
    gemm_wh_kernel<128, 16, 4, 2><<<grid, 256>>>(h2, W3);
    fe_kernel<16><<<(Hh * Nn) / 256, 256>>>(a3);
    agg_kernel<16, 4, 2><<<grid, 256>>>(h3, 64);

    final_kernel<<<(Nn * 32) / 256, 256>>>(Wlin, blin, out);
}

// round 3
// speedup vs baseline: 1.3576x; 1.3576x over previous
#include <cuda_runtime.h>
#include <math.h>
#include <stdint.h>

#define Nn 4096
#define Hh 4
#define NWORDS 128   // Nn/32

// ---------------- scratch (static device globals; no allocation) -------------
__device__ uint32_t g_mask[Nn * NWORDS];          // 2 MB packed adjacency
__device__ float g_Wh[Hh * Nn * 64];              // 4 MB, reused per stage (max O=64)
__device__ float2 g_E1[Hh * Nn];                  // (e^f1, e^{0.2 f1}) per node
__device__ float2 g_E2[Hh * Nn];                  // (e^f2, e^{0.2 f2}) per node
__device__ float g_h1[Nn * 256];
__device__ float g_h2[Nn * 128];
__device__ float g_h3[Nn * 64];

// ---------------- pack adjacency into bitmask --------------------------------
__global__ void pack_mask_kernel(const int* __restrict__ adj) {
    int idx = blockIdx.x * blockDim.x + threadIdx.x;  // one thread per 32-bit word
    int i = idx >> 7;
    int w = idx & 127;
    const int4* p = reinterpret_cast<const int4*>(adj + (size_t)i * Nn + (w << 5));
    uint32_t m = 0u;
#pragma unroll
    for (int q = 0; q < 8; q++) {
        int4 v = p[q];
        if (v.x) m |= 1u << (q * 4 + 0);
        if (v.y) m |= 1u << (q * 4 + 1);
        if (v.z) m |= 1u << (q * 4 + 2);
        if (v.w) m |= 1u << (q * 4 + 3);
    }
    g_mask[idx] = m;
}

// ---------------- Wh = x @ W[h]  (per head) ----------------------------------
template <int FIN, int O, int TM, int TN>
__global__ __launch_bounds__(256) void gemm_wh_kernel(const float* __restrict__ x,
                                                      const float* __restrict__ W) {
    const int h = blockIdx.y;
    const int n0 = blockIdx.x * 128;
    const int t = threadIdx.x;
    __shared__ float xs[32][132];  // [f][row], padded, 16B-aligned rows
    __shared__ float ws[32][O];    // [f][o]
    const int CG = O / TN;
    const int rg = t / CG, cg = t % CG;
    float acc[TM][TN];
#pragma unroll
    for (int k = 0; k < TM; k++)
#pragma unroll
        for (int u = 0; u < TN; u++) acc[k][u] = 0.f;
    const float* Wc = W + (size_t)h * FIN * O;
    for (int f0 = 0; f0 < FIN; f0 += 32) {
        __syncthreads();
#pragma unroll
        for (int k = 0; k < 16; k++) {
            int idx = t + k * 256;
            int f = idx & 31, row = idx >> 5;
            xs[f][row] = x[(size_t)(n0 + row) * FIN + f0 + f];
        }
#pragma unroll
        for (int k = 0; k < (32 * O) / 256; k++) {
            int idx = t + k * 256;
            int o = idx % O, f = idx / O;
            ws[f][o] = Wc[(size_t)(f0 + f) * O + o];
        }
        __syncthreads();
#pragma unroll 8
        for (int f = 0; f < 32; f++) {
            float xv[TM], wv[TN];
#pragma unroll
            for (int q = 0; q < TM / 4; q++)
                *(float4*)&xv[q * 4] = *(const float4*)&xs[f][rg * TM + q * 4];
            if (TN >= 4) {
#pragma unroll
                for (int q = 0; q < TN / 4; q++)
                    *(float4*)&wv[q * 4] = *(const float4*)&ws[f][cg * TN + q * 4];
            } else {
                *(float2*)&wv[0] = *(const float2*)&ws[f][cg * TN];
            }
#pragma unroll
            for (int k = 0; k < TM; k++)
#pragma unroll
                for (int u = 0; u < TN; u++) acc[k][u] += xv[k] * wv[u];
        }
    }
#pragma unroll
    for (int k = 0; k < TM; k++) {
        int n = n0 + rg * TM + k;
#pragma unroll
        for (int u = 0; u < TN; u++)
            g_Wh[((size_t)h * Nn + n) * O + cg * TN + u] = acc[k][u];
    }
}

// ---------------- per-node attention scalars ---------------------------------
// f1 = Wh . a[:O], f2 = Wh . a[O:]; store (e^f, e^{0.2f}) pairs.
template <int O>
__global__ void fe_kernel(const float* __restrict__ a) {
    int idx = blockIdx.x * 256 + threadIdx.x;  // over Hh*Nn
    int h = idx >> 12;                          // / Nn
    const float* wr = g_Wh + (size_t)idx * O;
    const float* av = a + h * 2 * O;
    float f1 = 0.f, f2 = 0.f;
#pragma unroll
    for (int o = 0; o < O; o++) {
        float w = wr[o];
        f1 += w * av[o];
        f2 += w * av[O + o];
    }
    g_E1[idx] = make_float2(expf(f1), expf(0.2f * f1));
    g_E2[idx] = make_float2(expf(f2), expf(0.2f * f2));
}

// ---------------- masked-softmax aggregation + ELU + head concat -------------
// exp(leaky(f1+f2)) = max(e^f1 * e^f2, e^{0.2f1} * e^{0.2f2})  (exp monotone,
// leaky(s) = max(s, 0.2s)), so no per-pair exp/compare on s is needed.
// CTA: (head h, 128 rows), 512 threads, j processed in chunks of JJ.
template <int O, int TM, int TN, int JJ>
__global__ __launch_bounds__(512) void agg_kernel(float* __restrict__ out, int HO) {
    const int h = blockIdx.y;
    const int n0 = blockIdx.x * 128;
    const int t = threadIdx.x;
    __shared__ float sWT[JJ][132];  // [jj][row], padded (528B rows, 16B aligned)
    __shared__ float sWh[JJ][O];    // [jj][o]
    __shared__ float sZpart[512];
    __shared__ float sZ[128];
    const int row = t & 127, seg = t >> 7;          // weight-compute mapping
    const float2 e1 = g_E1[h * Nn + n0 + row];
    const int CG = O / TN;
    const int rg = t / CG, cg = t % CG;             // consume mapping
    float acc[TM][TN];
#pragma unroll
    for (int k = 0; k < TM; k++)
#pragma unroll
        for (int u = 0; u < TN; u++) acc[k][u] = 0.f;
    float zloc = 0.f;
    const float* WhH = g_Wh + (size_t)h * Nn * O;
    const float2* E2H = g_E2 + h * Nn;
    const uint32_t* mrow = g_mask + (size_t)(n0 + row) * NWORDS;
    const int BPT = JJ / 4;  // weight bits per thread

    for (int c = 0; c < Nn / JJ; c++) {
        const int j0 = c * JJ;
        __syncthreads();  // protect sWT/sWh reuse from previous chunk
        // stage Wh chunk (coalesced)
#pragma unroll
        for (int k = 0; k < (JJ * O) / 512; k++) {
            int idx = t + k * 512;
            int o = idx % O, jj = idx / O;
            sWh[jj][o] = WhH[(size_t)(j0 + jj) * O + o];
        }
        // compute attention weights: thread handles BPT j's of its row
        {
            const int jjb = seg * BPT;
            uint32_t m = mrow[c * (JJ / 32) + (jjb >> 5)] >> (jjb & 31);
#pragma unroll
            for (int b = 0; b < BPT; b++) {
                int jj = jjb + b;
                float2 e2 = E2H[j0 + jj];  // uniform across warp -> broadcast
                float w = ((m >> b) & 1u) ? fmaxf(e1.x * e2.x, e1.y * e2.y) : 0.f;
                sWT[jj][row] = w;
                zloc += w;
            }
        }
        __syncthreads();
        // consume: acc += w * Wh
#pragma unroll 8
        for (int jj = 0; jj < JJ; jj++) {
            float wv[TM], bv[TN];
            if (TM == 1) {
                wv[0] = sWT[jj][rg];
            } else if (TM == 2) {
                *(float2*)&wv[0] = *(const float2*)&sWT[jj][rg * 2];
            } else {
#pragma unroll
                for (int q = 0; q < TM / 4; q++)
                    *(float4*)&wv[q * 4] = *(const float4*)&sWT[jj][rg * TM + q * 4];
            }
            if (TN == 2) {
                *(float2*)&bv[0] = *(const float2*)&sWh[jj][cg * TN];
            } else {
#pragma unroll
                for (int q = 0; q < TN / 4; q++)
                    *(float4*)&bv[q * 4] = *(const float4*)&sWh[jj][cg * TN + q * 4];
            }
#pragma unroll
            for (int k = 0; k < TM; k++)
#pragma unroll
                for (int u = 0; u < TN; u++) acc[k][u] += wv[k] * bv[u];
        }
    }
    sZpart[t] = zloc;
    __syncthreads();
    if (t < 128)
        sZ[t] = sZpart[t] + sZpart[t + 128] + sZpart[t + 256] + sZpart[t + 384];
    __syncthreads();
#pragma unroll
    for (int k = 0; k < TM; k++) {
        int r = rg * TM + k;
        float inv = 1.f / sZ[r];
#pragma unroll
        for (int u = 0; u < TN; u++) {
            float v = acc[k][u] * inv;
            v = v > 0.f ? v : expm1f(v);  // elu
            out[(size_t)(n0 + r) * HO + h * O + cg * TN + u] = v;
        }
    }
}

// ---------------- final linear + log_softmax ---------------------------------
__global__ void final_kernel(const float* __restrict__ Wlin,
                             const float* __restrict__ blin,
                             float* __restrict__ out) {
    int lane = threadIdx.x & 31;
    int n = (blockIdx.x * blockDim.x + threadIdx.x) >> 5;  // one warp per row
    const float* hr = g_h3 + (size_t)n * 64;
    float v1 = -INFINITY;
    float a0 = blin[lane];
    float a1v = (lane < 8) ? blin[lane + 32] : 0.f;
#pragma unroll 16
    for (int k = 0; k < 64; k++) {
        float hv = hr[k];
        a0 += hv * Wlin[k * 40 + lane];
        if (lane < 8) a1v += hv * Wlin[k * 40 + lane + 32];
    }
    float v0 = a0;
    if (lane < 8) v1 = a1v;
    float m = fmaxf(v0, v1);
#pragma unroll
    for (int off = 16; off; off >>= 1) m = fmaxf(m, __shfl_xor_sync(0xffffffffu, m, off));
    float e = expf(v0 - m) + ((lane < 8) ? expf(v1 - m) : 0.f);
#pragma unroll
    for (int off = 16; off; off >>= 1) e += __shfl_xor_sync(0xffffffffu, e, off);
    float lse = m + logf(e);
    out[(size_t)n * 40 + lane] = v0 - lse;
    if (lane < 8) out[(size_t)n * 40 + lane + 32] = v1 - lse;
}

// ---------------- launch -----------------------------------------------------
extern "C" void kernel_launch(void* const* d_in, const int* in_sizes, int n_in,
                              void* d_out, int out_size) {
    const float* x    = (const float*)d_in[0];
    const int*   adj  = (const int*)d_in[1];
    const float* W1   = (const float*)d_in[2];
    const float* a1   = (const float*)d_in[3];
    const float* W2   = (const float*)d_in[4];
    const float* a2   = (const float*)d_in[5];
    const float* W3   = (const float*)d_in[6];
    const float* a3   = (const float*)d_in[7];
    const float* Wlin = (const float*)d_in[8];
    const float* blin = (const float*)d_in[9];
    float* out = (float*)d_out;

    float *h1, *h2, *h3;
    cudaGetSymbolAddress((void**)&h1, g_h1);
    cudaGetSymbolAddress((void**)&h2, g_h2);
    cudaGetSymbolAddress((void**)&h3, g_h3);

    pack_mask_kernel<<<(Nn * NWORDS) / 256, 256>>>(adj);

    dim3 grid(Nn / 128, Hh);

    // stage 1: Fin=512, O=64
    gemm_wh_kernel<512, 64, 8, 4><<<grid, 256>>>(x, W1);
    fe_kernel<64><<<(Hh * Nn) / 256, 256>>>(a1);
    agg_kernel<64, 4, 4, 32><<<grid, 512>>>(h1, 256);

    // stage 2: Fin=256, O=32
    gemm_wh_kernel<256, 32, 4, 4><<<grid, 256>>>(h1, W2);
    fe_kernel<32><<<(Hh * Nn) / 256, 256>>>(a2);
    agg_kernel<32, 2, 4, 64><<<grid, 512>>>(h2, 128);

    // stage 3: Fin=128, O=16
    gemm_wh_kernel<128, 16, 4, 2><<<grid, 256>>>(h2, W3);
    fe_kernel<16><<<(Hh * Nn) / 256, 256>>>(a3);
    agg_kernel<16, 1, 4, 64><<<grid, 512>>>(h3, 64);

    final_kernel<<<(Nn * 32) / 256, 256>>>(Wlin, blin, out);
}

// round 4
// speedup vs baseline: 2.3267x; 1.7139x over previous
#include <cuda_runtime.h>
#include <math.h>
#include <stdint.h>

#define Nn 4096
#define Hh 4
#define NWORDS 128   // Nn/32

// ---------------- scratch (static device globals; no allocation) -------------
__device__ uint32_t g_mask[Nn * NWORDS];          // 2 MB packed adjacency
__device__ float g_Wh[Hh * Nn * 64];              // 4 MB, reused per stage (max O=64)
__device__ float2 g_E1[Hh * Nn];                  // (e^f1, e^{0.2 f1}) per node
__device__ float2 g_E2[Hh * Nn];                  // (e^f2, e^{0.2 f2}) per node
__device__ float g_h1[Nn * 256];
__device__ float g_h2[Nn * 128];
__device__ float g_h3[Nn * 64];

// ---------------- pack adjacency into bitmask --------------------------------
__global__ void pack_mask_kernel(const int* __restrict__ adj) {
    int idx = blockIdx.x * blockDim.x + threadIdx.x;  // one thread per 32-bit word
    int i = idx >> 7;
    int w = idx & 127;
    const int4* p = reinterpret_cast<const int4*>(adj + (size_t)i * Nn + (w << 5));
    uint32_t m = 0u;
#pragma unroll
    for (int q = 0; q < 8; q++) {
        int4 v = p[q];
        if (v.x) m |= 1u << (q * 4 + 0);
        if (v.y) m |= 1u << (q * 4 + 1);
        if (v.z) m |= 1u << (q * 4 + 2);
        if (v.w) m |= 1u << (q * 4 + 3);
    }
    g_mask[idx] = m;
}

// ---------------- Wh = x @ W[h]  (per head) ----------------------------------
template <int FIN, int O, int TM, int TN>
__global__ __launch_bounds__(256) void gemm_wh_kernel(const float* __restrict__ x,
                                                      const float* __restrict__ W) {
    const int h = blockIdx.y;
    const int n0 = blockIdx.x * 128;
    const int t = threadIdx.x;
    __shared__ float xs[32][132];  // [f][row], padded, 16B-aligned rows
    __shared__ float ws[32][O];    // [f][o]
    const int CG = O / TN;
    const int rg = t / CG, cg = t % CG;
    float acc[TM][TN];
#pragma unroll
    for (int k = 0; k < TM; k++)
#pragma unroll
        for (int u = 0; u < TN; u++) acc[k][u] = 0.f;
    const float* Wc = W + (size_t)h * FIN * O;
    for (int f0 = 0; f0 < FIN; f0 += 32) {
        __syncthreads();
#pragma unroll
        for (int k = 0; k < 16; k++) {
            int idx = t + k * 256;
            int f = idx & 31, row = idx >> 5;
            xs[f][row] = x[(size_t)(n0 + row) * FIN + f0 + f];
        }
#pragma unroll
        for (int k = 0; k < (32 * O) / 256; k++) {
            int idx = t + k * 256;
            int o = idx % O, f = idx / O;
            ws[f][o] = Wc[(size_t)(f0 + f) * O + o];
        }
        __syncthreads();
#pragma unroll 8
        for (int f = 0; f < 32; f++) {
            float xv[TM], wv[TN];
#pragma unroll
            for (int q = 0; q < TM / 4; q++)
                *(float4*)&xv[q * 4] = *(const float4*)&xs[f][rg * TM + q * 4];
            if (TN >= 4) {
#pragma unroll
                for (int q = 0; q < TN / 4; q++)
                    *(float4*)&wv[q * 4] = *(const float4*)&ws[f][cg * TN + q * 4];
            } else {
                *(float2*)&wv[0] = *(const float2*)&ws[f][cg * TN];
            }
#pragma unroll
            for (int k = 0; k < TM; k++)
#pragma unroll
                for (int u = 0; u < TN; u++) acc[k][u] += xv[k] * wv[u];
        }
    }
#pragma unroll
    for (int k = 0; k < TM; k++) {
        int n = n0 + rg * TM + k;
#pragma unroll
        for (int u = 0; u < TN; u++)
            g_Wh[((size_t)h * Nn + n) * O + cg * TN + u] = acc[k][u];
    }
}

// ---------------- per-node attention scalars ---------------------------------
template <int O>
__global__ void fe_kernel(const float* __restrict__ a) {
    int idx = blockIdx.x * 256 + threadIdx.x;  // over Hh*Nn
    int h = idx >> 12;                          // / Nn
    const float* wr = g_Wh + (size_t)idx * O;
    const float* av = a + h * 2 * O;
    float f1 = 0.f, f2 = 0.f;
#pragma unroll
    for (int o = 0; o < O; o++) {
        float w = wr[o];
        f1 += w * av[o];
        f2 += w * av[O + o];
    }
    g_E1[idx] = make_float2(expf(f1), expf(0.2f * f1));
    g_E2[idx] = make_float2(expf(f2), expf(0.2f * f2));
}

// ---------------- tf32 tensor-core masked-softmax aggregation ----------------
// exp(leaky(f1+f2)) = max(e^f1*e^f2, e^{0.2f1}*e^{0.2f2}).
// Weights materialized into smem A[row][k] (tf32-rounded), Wh staged B[k][o];
// consume via mma.sync.m16n8k8 tf32, accumulate fp32, normalize+ELU epilogue.
template <int O>
__global__ __launch_bounds__(512) void agg_mma_kernel(float* __restrict__ out, int HO) {
    constexpr int NW_N = (O == 16) ? 2 : 4;     // warp grid cols
    constexpr int NW_M = 16 / NW_N;             // warp grid rows
    constexpr int WM = 128 / NW_M;              // rows per warp
    constexpr int WN = O / NW_N;                // cols per warp
    constexpr int MT = WM / 16;                 // m16 tiles per warp
    constexpr int NT = WN / 8;                  // n8 tiles per warp
    constexpr int SB = O + 8;                   // sWh stride (conflict-free)

    __shared__ float sW[128][36];               // weights [row][k], stride 36
    __shared__ float sWh[32][SB];               // Wh chunk [k][o]
    __shared__ float sZq[512];
    __shared__ float sZ[128];

    const int h = blockIdx.y;
    const int n0 = blockIdx.x * 128;
    const int t = threadIdx.x;
    const int lane = t & 31, wid = t >> 5;
    const int wm = wid / NW_N, wn = wid % NW_N;
    const int row0 = wm * WM, col0 = wn * WN;

    // weight-producer mapping: 4 threads per row, strided k
    const int rq = t >> 2, kq = t & 3;
    const float2 e1 = g_E1[h * Nn + n0 + rq];
    const float* WhH = g_Wh + (size_t)h * Nn * O;
    const float2* E2H = g_E2 + h * Nn;
    const uint32_t* mrow = g_mask + (size_t)(n0 + rq) * NWORDS;

    float acc[MT][NT][4];
#pragma unroll
    for (int mt = 0; mt < MT; mt++)
#pragma unroll
        for (int nt = 0; nt < NT; nt++)
#pragma unroll
            for (int q = 0; q < 4; q++) acc[mt][nt][q] = 0.f;
    float zloc = 0.f;

    for (int c = 0; c < NWORDS; c++) {
        const int j0 = c << 5;
        __syncthreads();  // previous chunk's mma reads finished
        // stage Wh chunk (tf32-rounded), 8*O float4 elements
        if (t < 8 * O) {
            int o4 = t % (O / 4), jj = t / (O / 4);
            float4 v = *(const float4*)&WhH[(size_t)(j0 + jj) * O + o4 * 4];
            uint32_t c0, c1, c2, c3;
            asm("cvt.rna.tf32.f32 %0, %1;" : "=r"(c0) : "f"(v.x));
            asm("cvt.rna.tf32.f32 %0, %1;" : "=r"(c1) : "f"(v.y));
            asm("cvt.rna.tf32.f32 %0, %1;" : "=r"(c2) : "f"(v.z));
            asm("cvt.rna.tf32.f32 %0, %1;" : "=r"(c3) : "f"(v.w));
            float4 sv = make_float4(__uint_as_float(c0), __uint_as_float(c1),
                                    __uint_as_float(c2), __uint_as_float(c3));
            *(float4*)&sWh[jj][o4 * 4] = sv;
        }
        // compute weights for this chunk (8 per thread, strided k)
        {
            uint32_t m = mrow[c];
#pragma unroll
            for (int b = 0; b < 8; b++) {
                int k = kq + b * 4;
                float2 e2 = E2H[j0 + k];
                float w = 0.f;
                if ((m >> k) & 1u) w = fmaxf(e1.x * e2.x, e1.y * e2.y);
                uint32_t wb;
                asm("cvt.rna.tf32.f32 %0, %1;" : "=r"(wb) : "f"(w));
                float wf = __uint_as_float(wb);
                sW[rq][k] = wf;
                zloc += wf;
            }
        }
        __syncthreads();
        // consume: 4 k-steps of 8, mma m16n8k8 tf32
#pragma unroll
        for (int ks = 0; ks < 4; ks++) {
            const int k0 = ks * 8;
            uint32_t a[MT][4], bb[NT][2];
            const int kk = k0 + (lane & 3);
            const int rl = lane >> 2;
#pragma unroll
            for (int mt = 0; mt < MT; mt++) {
                int r = row0 + mt * 16 + rl;
                a[mt][0] = __float_as_uint(sW[r][kk]);
                a[mt][1] = __float_as_uint(sW[r + 8][kk]);
                a[mt][2] = __float_as_uint(sW[r][kk + 4]);
                a[mt][3] = __float_as_uint(sW[r + 8][kk + 4]);
            }
#pragma unroll
            for (int nt = 0; nt < NT; nt++) {
                int n = col0 + nt * 8 + rl;
                bb[nt][0] = __float_as_uint(sWh[kk][n]);
                bb[nt][1] = __float_as_uint(sWh[kk + 4][n]);
            }
#pragma unroll
            for (int mt = 0; mt < MT; mt++)
#pragma unroll
                for (int nt = 0; nt < NT; nt++)
                    asm volatile(
                        "mma.sync.aligned.m16n8k8.row.col.f32.tf32.tf32.f32 "
                        "{%0,%1,%2,%3}, {%4,%5,%6,%7}, {%8,%9}, {%0,%1,%2,%3};"
                        : "+f"(acc[mt][nt][0]), "+f"(acc[mt][nt][1]),
                          "+f"(acc[mt][nt][2]), "+f"(acc[mt][nt][3])
                        : "r"(a[mt][0]), "r"(a[mt][1]), "r"(a[mt][2]), "r"(a[mt][3]),
                          "r"(bb[nt][0]), "r"(bb[nt][1]));
        }
    }
    // reduce Z per row (4 producer threads per row)
    sZq[t] = zloc;
    __syncthreads();
    if (t < 128)
        sZ[t] = sZq[t * 4] + sZq[t * 4 + 1] + sZq[t * 4 + 2] + sZq[t * 4 + 3];
    __syncthreads();
    // epilogue: normalize, ELU, head-concat store
#pragma unroll
    for (int mt = 0; mt < MT; mt++) {
        int r = row0 + mt * 16 + (lane >> 2);
        float iz0 = 1.f / sZ[r];
        float iz1 = 1.f / sZ[r + 8];
#pragma unroll
        for (int nt = 0; nt < NT; nt++) {
            int cb = col0 + nt * 8 + (lane & 3) * 2;
            float v0 = acc[mt][nt][0] * iz0;
            float v1 = acc[mt][nt][1] * iz0;
            float v2 = acc[mt][nt][2] * iz1;
            float v3 = acc[mt][nt][3] * iz1;
            v0 = v0 > 0.f ? v0 : expm1f(v0);
            v1 = v1 > 0.f ? v1 : expm1f(v1);
            v2 = v2 > 0.f ? v2 : expm1f(v2);
            v3 = v3 > 0.f ? v3 : expm1f(v3);
            *(float2*)&out[(size_t)(n0 + r) * HO + h * O + cb] = make_float2(v0, v1);
            *(float2*)&out[(size_t)(n0 + r + 8) * HO + h * O + cb] = make_float2(v2, v3);
        }
    }
}

// ---------------- final linear + log_softmax ---------------------------------
__global__ void final_kernel(const float* __restrict__ Wlin,
                             const float* __restrict__ blin,
                             float* __restrict__ out) {
    int lane = threadIdx.x & 31;
    int n = (blockIdx.x * blockDim.x + threadIdx.x) >> 5;  // one warp per row
    const float* hr = g_h3 + (size_t)n * 64;
    float v1 = -INFINITY;
    float a0 = blin[lane];
    float a1v = (lane < 8) ? blin[lane + 32] : 0.f;
#pragma unroll 16
    for (int k = 0; k < 64; k++) {
        float hv = hr[k];
        a0 += hv * Wlin[k * 40 + lane];
        if (lane < 8) a1v += hv * Wlin[k * 40 + lane + 32];
    }
    float v0 = a0;
    if (lane < 8) v1 = a1v;
    float m = fmaxf(v0, v1);
#pragma unroll
    for (int off = 16; off; off >>= 1) m = fmaxf(m, __shfl_xor_sync(0xffffffffu, m, off));
    float e = expf(v0 - m) + ((lane < 8) ? expf(v1 - m) : 0.f);
#pragma unroll
    for (int off = 16; off; off >>= 1) e += __shfl_xor_sync(0xffffffffu, e, off);
    float lse = m + logf(e);
    out[(size_t)n * 40 + lane] = v0 - lse;
    if (lane < 8) out[(size_t)n * 40 + lane + 32] = v1 - lse;
}

// ---------------- launch -----------------------------------------------------
extern "C" void kernel_launch(void* const* d_in, const int* in_sizes, int n_in,
                              void* d_out, int out_size) {
    const float* x    = (const float*)d_in[0];
    const int*   adj  = (const int*)d_in[1];
    const float* W1   = (const float*)d_in[2];
    const float* a1   = (const float*)d_in[3];
    const float* W2   = (const float*)d_in[4];
    const float* a2   = (const float*)d_in[5];
    const float* W3   = (const float*)d_in[6];
    const float* a3   = (const float*)d_in[7];
    const float* Wlin = (const float*)d_in[8];
    const float* blin = (const float*)d_in[9];
    float* out = (float*)d_out;

    float *h1, *h2, *h3;
    cudaGetSymbolAddress((void**)&h1, g_h1);
    cudaGetSymbolAddress((void**)&h2, g_h2);
    cudaGetSymbolAddress((void**)&h3, g_h3);

    pack_mask_kernel<<<(Nn * NWORDS) / 256, 256>>>(adj);

    dim3 grid(Nn / 128, Hh);

    // stage 1: Fin=512, O=64
    gemm_wh_kernel<512, 64, 8, 4><<<grid, 256>>>(x, W1);
    fe_kernel<64><<<(Hh * Nn) / 256, 256>>>(a1);
    agg_mma_kernel<64><<<grid, 512>>>(h1, 256);

    // stage 2: Fin=256, O=32
    gemm_wh_kernel<256, 32, 4, 4><<<grid, 256>>>(h1, W2);
    fe_kernel<32><<<(Hh * Nn) / 256, 256>>>(a2);
    agg_mma_kernel<32><<<grid, 512>>>(h2, 128);

    // stage 3: Fin=128, O=16
    gemm_wh_kernel<128, 16, 4, 2><<<grid, 256>>>(h2, W3);
    fe_kernel<16><<<(Hh * Nn) / 256, 256>>>(a3);
    agg_mma_kernel<16><<<grid, 512>>>(h3, 64);

    final_kernel<<<(Nn * 32) / 256, 256>>>(Wlin, blin, out);
}

// round 5
// speedup vs baseline: 2.4246x; 1.0421x over previous
#include <cuda_runtime.h>
#include <math.h>
#include <stdint.h>

#define Nn 4096
#define Hh 4
#define NWORDS 128   // Nn/32

// ---------------- scratch (static device globals; no allocation) -------------
__device__ uint32_t g_mask[Nn * NWORDS];          // 2 MB packed adjacency
__device__ float g_Wh[Hh * Nn * 64];              // 4 MB, reused per stage (max O=64)
__device__ float2 g_E1[Hh * Nn];                  // (e^f1, e^{0.2 f1}) per node
__device__ float2 g_E2[Hh * Nn];                  // (e^f2, e^{0.2 f2}) per node
__device__ float g_h1[Nn * 256];
__device__ float g_h2[Nn * 128];
__device__ float g_h3[Nn * 64];

// ---------------- pack adjacency into bitmask --------------------------------
__global__ void pack_mask_kernel(const int* __restrict__ adj) {
    int idx = blockIdx.x * blockDim.x + threadIdx.x;  // one thread per 32-bit word
    int i = idx >> 7;
    int w = idx & 127;
    const int4* p = reinterpret_cast<const int4*>(adj + (size_t)i * Nn + (w << 5));
    uint32_t m = 0u;
#pragma unroll
    for (int q = 0; q < 8; q++) {
        int4 v = p[q];
        if (v.x) m |= 1u << (q * 4 + 0);
        if (v.y) m |= 1u << (q * 4 + 1);
        if (v.z) m |= 1u << (q * 4 + 2);
        if (v.w) m |= 1u << (q * 4 + 3);
    }
    g_mask[idx] = m;
}

// ---------------- Wh = x @ W[h]  (per head) ----------------------------------
template <int FIN, int O, int TM, int TN>
__global__ __launch_bounds__(256) void gemm_wh_kernel(const float* __restrict__ x,
                                                      const float* __restrict__ W) {
    const int h = blockIdx.y;
    const int n0 = blockIdx.x * 128;
    const int t = threadIdx.x;
    __shared__ float xs[32][132];  // [f][row], padded, 16B-aligned rows
    __shared__ float ws[32][O];    // [f][o]
    const int CG = O / TN;
    const int rg = t / CG, cg = t % CG;
    float acc[TM][TN];
#pragma unroll
    for (int k = 0; k < TM; k++)
#pragma unroll
        for (int u = 0; u < TN; u++) acc[k][u] = 0.f;
    const float* Wc = W + (size_t)h * FIN * O;
    for (int f0 = 0; f0 < FIN; f0 += 32) {
        __syncthreads();
#pragma unroll
        for (int k = 0; k < 16; k++) {
            int idx = t + k * 256;
            int f = idx & 31, row = idx >> 5;
            xs[f][row] = x[(size_t)(n0 + row) * FIN + f0 + f];
        }
#pragma unroll
        for (int k = 0; k < (32 * O) / 256; k++) {
            int idx = t + k * 256;
            int o = idx % O, f = idx / O;
            ws[f][o] = Wc[(size_t)(f0 + f) * O + o];
        }
        __syncthreads();
#pragma unroll 8
        for (int f = 0; f < 32; f++) {
            float xv[TM], wv[TN];
#pragma unroll
            for (int q = 0; q < TM / 4; q++)
                *(float4*)&xv[q * 4] = *(const float4*)&xs[f][rg * TM + q * 4];
            if (TN >= 4) {
#pragma unroll
                for (int q = 0; q < TN / 4; q++)
                    *(float4*)&wv[q * 4] = *(const float4*)&ws[f][cg * TN + q * 4];
            } else {
                *(float2*)&wv[0] = *(const float2*)&ws[f][cg * TN];
            }
#pragma unroll
            for (int k = 0; k < TM; k++)
#pragma unroll
                for (int u = 0; u < TN; u++) acc[k][u] += xv[k] * wv[u];
        }
    }
#pragma unroll
    for (int k = 0; k < TM; k++) {
        int n = n0 + rg * TM + k;
#pragma unroll
        for (int u = 0; u < TN; u++)
            g_Wh[((size_t)h * Nn + n) * O + cg * TN + u] = acc[k][u];
    }
}

// ---------------- per-node attention scalars ---------------------------------
template <int O>
__global__ void fe_kernel(const float* __restrict__ a) {
    int idx = blockIdx.x * 256 + threadIdx.x;  // over Hh*Nn
    int h = idx >> 12;                          // / Nn
    const float* wr = g_Wh + (size_t)idx * O;
    const float* av = a + h * 2 * O;
    float f1 = 0.f, f2 = 0.f;
#pragma unroll
    for (int o = 0; o < O; o++) {
        float w = wr[o];
        f1 += w * av[o];
        f2 += w * av[O + o];
    }
    g_E1[idx] = make_float2(expf(f1), expf(0.2f * f1));
    g_E2[idx] = make_float2(expf(f2), expf(0.2f * f2));
}

// ---------------- tf32 tensor-core masked-softmax aggregation ----------------
// Software-pipelined: chunk c+1's weights & Wh are produced into registers
// (global loads overlapped with chunk c's MMAs), then stored to smem in a
// short STS phase between barriers.
template <int O>
__global__ __launch_bounds__(512) void agg_mma_kernel(float* __restrict__ out, int HO) {
    constexpr int NW_N = (O == 16) ? 2 : 4;     // warp grid cols
    constexpr int NW_M = 16 / NW_N;             // warp grid rows
    constexpr int WM = 128 / NW_M;              // rows per warp
    constexpr int WN = O / NW_N;                // cols per warp
    constexpr int MT = WM / 16;                 // m16 tiles per warp
    constexpr int NT = WN / 8;                  // n8 tiles per warp
    constexpr int SB = O + 8;                   // sWh stride (conflict-free)

    __shared__ float sW[128][36];               // weights [row][k], stride 36
    __shared__ float sWh[32][SB];               // Wh chunk [k][o]
    __shared__ float sZq[512];
    __shared__ float sZ[128];

    const int h = blockIdx.y;
    const int n0 = blockIdx.x * 128;
    const int t = threadIdx.x;
    const int lane = t & 31, wid = t >> 5;
    const int wm = wid / NW_N, wn = wid % NW_N;
    const int row0 = wm * WM, col0 = wn * WN;

    // weight-producer mapping: 4 threads per row, strided k
    const int rq = t >> 2, kq = t & 3;
    const float2 e1 = g_E1[h * Nn + n0 + rq];
    const float* WhH = g_Wh + (size_t)h * Nn * O;
    const float2* E2H = g_E2 + h * Nn;
    const uint32_t* mrow = g_mask + (size_t)(n0 + rq) * NWORDS;

    // Wh staging mapping
    const bool wh_act = (t < 8 * O);
    const int o4 = t % (O / 4), jw = t / (O / 4);

    float acc[MT][NT][4];
#pragma unroll
    for (int mt = 0; mt < MT; mt++)
#pragma unroll
        for (int nt = 0; nt < NT; nt++)
#pragma unroll
            for (int q = 0; q < 4; q++) acc[mt][nt][q] = 0.f;
    float zloc = 0.f;

    float wreg[8];
    float4 whreg = make_float4(0.f, 0.f, 0.f, 0.f);

    auto produce = [&](int c) {
        const int j0 = c << 5;
        uint32_t m = mrow[c];
#pragma unroll
        for (int b = 0; b < 8; b++) {
            int k = kq + b * 4;
            float2 e2 = E2H[j0 + k];
            float w = ((m >> k) & 1u) ? fmaxf(e1.x * e2.x, e1.y * e2.y) : 0.f;
            uint32_t wb;
            asm("cvt.rna.tf32.f32 %0, %1;" : "=r"(wb) : "f"(w));
            wreg[b] = __uint_as_float(wb);
        }
        if (wh_act) {
            float4 v = *(const float4*)&WhH[(size_t)(j0 + jw) * O + o4 * 4];
            uint32_t c0, c1, c2, c3;
            asm("cvt.rna.tf32.f32 %0, %1;" : "=r"(c0) : "f"(v.x));
            asm("cvt.rna.tf32.f32 %0, %1;" : "=r"(c1) : "f"(v.y));
            asm("cvt.rna.tf32.f32 %0, %1;" : "=r"(c2) : "f"(v.z));
            asm("cvt.rna.tf32.f32 %0, %1;" : "=r"(c3) : "f"(v.w));
            whreg = make_float4(__uint_as_float(c0), __uint_as_float(c1),
                                __uint_as_float(c2), __uint_as_float(c3));
        }
    };

    produce(0);

    for (int c = 0; c < NWORDS; c++) {
        __syncthreads();  // consume of chunk c-1 finished everywhere
        // short store phase: regs -> smem
#pragma unroll
        for (int b = 0; b < 8; b++) {
            sW[rq][kq + b * 4] = wreg[b];
            zloc += wreg[b];
        }
        if (wh_act) *(float4*)&sWh[jw][o4 * 4] = whreg;
        __syncthreads();  // stores visible
        // kick off next chunk's loads; latency overlaps the MMAs below
        if (c + 1 < NWORDS) produce(c + 1);
        // consume: 4 k-steps of 8, mma m16n8k8 tf32
#pragma unroll
        for (int ks = 0; ks < 4; ks++) {
            const int k0 = ks * 8;
            uint32_t a[MT][4], bb[NT][2];
            const int kk = k0 + (lane & 3);
            const int rl = lane >> 2;
#pragma unroll
            for (int mt = 0; mt < MT; mt++) {
                int r = row0 + mt * 16 + rl;
                a[mt][0] = __float_as_uint(sW[r][kk]);
                a[mt][1] = __float_as_uint(sW[r + 8][kk]);
                a[mt][2] = __float_as_uint(sW[r][kk + 4]);
                a[mt][3] = __float_as_uint(sW[r + 8][kk + 4]);
            }
#pragma unroll
            for (int nt = 0; nt < NT; nt++) {
                int n = col0 + nt * 8 + rl;
                bb[nt][0] = __float_as_uint(sWh[kk][n]);
                bb[nt][1] = __float_as_uint(sWh[kk + 4][n]);
            }
#pragma unroll
            for (int mt = 0; mt < MT; mt++)
#pragma unroll
                for (int nt = 0; nt < NT; nt++)
                    asm volatile(
                        "mma.sync.aligned.m16n8k8.row.col.f32.tf32.tf32.f32 "
                        "{%0,%1,%2,%3}, {%4,%5,%6,%7}, {%8,%9}, {%0,%1,%2,%3};"
                        : "+f"(acc[mt][nt][0]), "+f"(acc[mt][nt][1]),
                          "+f"(acc[mt][nt][2]), "+f"(acc[mt][nt][3])
                        : "r"(a[mt][0]), "r"(a[mt][1]), "r"(a[mt][2]), "r"(a[mt][3]),
                          "r"(bb[nt][0]), "r"(bb[nt][1]));
        }
    }
    // reduce Z per row (4 producer threads per row)
    sZq[t] = zloc;
    __syncthreads();
    if (t < 128)
        sZ[t] = sZq[t * 4] + sZq[t * 4 + 1] + sZq[t * 4 + 2] + sZq[t * 4 + 3];
    __syncthreads();
    // epilogue: normalize, ELU, head-concat store
#pragma unroll
    for (int mt = 0; mt < MT; mt++) {
        int r = row0 + mt * 16 + (lane >> 2);
        float iz0 = 1.f / sZ[r];
        float iz1 = 1.f / sZ[r + 8];
#pragma unroll
        for (int nt = 0; nt < NT; nt++) {
            int cb = col0 + nt * 8 + (lane & 3) * 2;
            float v0 = acc[mt][nt][0] * iz0;
            float v1 = acc[mt][nt][1] * iz0;
            float v2 = acc[mt][nt][2] * iz1;
            float v3 = acc[mt][nt][3] * iz1;
            v0 = v0 > 0.f ? v0 : expm1f(v0);
            v1 = v1 > 0.f ? v1 : expm1f(v1);
            v2 = v2 > 0.f ? v2 : expm1f(v2);
            v3 = v3 > 0.f ? v3 : expm1f(v3);
            *(float2*)&out[(size_t)(n0 + r) * HO + h * O + cb] = make_float2(v0, v1);
            *(float2*)&out[(size_t)(n0 + r + 8) * HO + h * O + cb] = make_float2(v2, v3);
        }
    }
}

// ---------------- final linear + log_softmax ---------------------------------
__global__ void final_kernel(const float* __restrict__ Wlin,
                             const float* __restrict__ blin,
                             float* __restrict__ out) {
    int lane = threadIdx.x & 31;
    int n = (blockIdx.x * blockDim.x + threadIdx.x) >> 5;  // one warp per row
    const float* hr = g_h3 + (size_t)n * 64;
    float v1 = -INFINITY;
    float a0 = blin[lane];
    float a1v = (lane < 8) ? blin[lane + 32] : 0.f;
#pragma unroll 16
    for (int k = 0; k < 64; k++) {
        float hv = hr[k];
        a0 += hv * Wlin[k * 40 + lane];
        if (lane < 8) a1v += hv * Wlin[k * 40 + lane + 32];
    }
    float v0 = a0;
    if (lane < 8) v1 = a1v;
    float m = fmaxf(v0, v1);
#pragma unroll
    for (int off = 16; off; off >>= 1) m = fmaxf(m, __shfl_xor_sync(0xffffffffu, m, off));
    float e = expf(v0 - m) + ((lane < 8) ? expf(v1 - m) : 0.f);
#pragma unroll
    for (int off = 16; off; off >>= 1) e += __shfl_xor_sync(0xffffffffu, e, off);
    float lse = m + logf(e);
    out[(size_t)n * 40 + lane] = v0 - lse;
    if (lane < 8) out[(size_t)n * 40 + lane + 32] = v1 - lse;
}

// ---------------- launch -----------------------------------------------------
extern "C" void kernel_launch(void* const* d_in, const int* in_sizes, int n_in,
                              void* d_out, int out_size) {
    const float* x    = (const float*)d_in[0];
    const int*   adj  = (const int*)d_in[1];
    const float* W1   = (const float*)d_in[2];
    const float* a1   = (const float*)d_in[3];
    const float* W2   = (const float*)d_in[4];
    const float* a2   = (const float*)d_in[5];
    const float* W3   = (const float*)d_in[6];
    const float* a3   = (const float*)d_in[7];
    const float* Wlin = (const float*)d_in[8];
    const float* blin = (const float*)d_in[9];
    float* out = (float*)d_out;

    float *h1, *h2, *h3;
    cudaGetSymbolAddress((void**)&h1, g_h1);
    cudaGetSymbolAddress((void**)&h2, g_h2);
    cudaGetSymbolAddress((void**)&h3, g_h3);

    pack_mask_kernel<<<(Nn * NWORDS) / 256, 256>>>(adj);

    dim3 grid(Nn / 128, Hh);

    // stage 1: Fin=512, O=64
    gemm_wh_kernel<512, 64, 8, 4><<<grid, 256>>>(x, W1);
    fe_kernel<64><<<(Hh * Nn) / 256, 256>>>(a1);
    agg_mma_kernel<64><<<grid, 512>>>(h1, 256);

    // stage 2: Fin=256, O=32
    gemm_wh_kernel<256, 32, 4, 4><<<grid, 256>>>(h1, W2);
    fe_kernel<32><<<(Hh * Nn) / 256, 256>>>(a2);
    agg_mma_kernel<32><<<grid, 512>>>(h2, 128);

    // stage 3: Fin=128, O=16
    gemm_wh_kernel<128, 16, 4, 2><<<grid, 256>>>(h2, W3);
    fe_kernel<16><<<(Hh * Nn) / 256, 256>>>(a3);
    agg_mma_kernel<16><<<grid, 512>>>(h3, 64);

    final_kernel<<<(Nn * 32) / 256, 256>>>(Wlin, blin, out);
}

// round 6
// speedup vs baseline: 2.5300x; 1.0435x over previous
#include <cuda_runtime.h>
#include <math.h>
#include <stdint.h>

#define Nn 4096
#define Hh 4
#define NWORDS 128   // Nn/32

// ---------------- scratch (static device globals; no allocation) -------------
__device__ uint32_t g_mask[Nn * NWORDS];          // 2 MB packed adjacency
__device__ float g_Wh[Hh * Nn * 64];              // 4 MB, reused per stage (max O=64)
__device__ float2 g_E1[Hh * Nn];                  // (e^f1, e^{0.2 f1}) per node
__device__ float2 g_E2[Hh * Nn];                  // (e^f2, e^{0.2 f2}) per node
__device__ float g_h1[Nn * 256];
__device__ float g_h2[Nn * 128];
__device__ float g_h3[Nn * 64];

// ---------------- pack adjacency into bitmask --------------------------------
__global__ void pack_mask_kernel(const int* __restrict__ adj) {
    int idx = blockIdx.x * blockDim.x + threadIdx.x;  // one thread per 32-bit word
    int i = idx >> 7;
    int w = idx & 127;
    const int4* p = reinterpret_cast<const int4*>(adj + (size_t)i * Nn + (w << 5));
    uint32_t m = 0u;
#pragma unroll
    for (int q = 0; q < 8; q++) {
        int4 v = p[q];
        if (v.x) m |= 1u << (q * 4 + 0);
        if (v.y) m |= 1u << (q * 4 + 1);
        if (v.z) m |= 1u << (q * 4 + 2);
        if (v.w) m |= 1u << (q * 4 + 3);
    }
    g_mask[idx] = m;
}

// ---------------- Wh = x @ W[h]  (per head) ----------------------------------
template <int FIN, int O, int TM, int TN>
__global__ __launch_bounds__(256) void gemm_wh_kernel(const float* __restrict__ x,
                                                      const float* __restrict__ W) {
    const int h = blockIdx.y;
    const int n0 = blockIdx.x * 128;
    const int t = threadIdx.x;
    __shared__ float xs[32][132];  // [f][row], padded, 16B-aligned rows
    __shared__ float ws[32][O];    // [f][o]
    const int CG = O / TN;
    const int rg = t / CG, cg = t % CG;
    float acc[TM][TN];
#pragma unroll
    for (int k = 0; k < TM; k++)
#pragma unroll
        for (int u = 0; u < TN; u++) acc[k][u] = 0.f;
    const float* Wc = W + (size_t)h * FIN * O;
    for (int f0 = 0; f0 < FIN; f0 += 32) {
        __syncthreads();
#pragma unroll
        for (int k = 0; k < 16; k++) {
            int idx = t + k * 256;
            int f = idx & 31, row = idx >> 5;
            xs[f][row] = x[(size_t)(n0 + row) * FIN + f0 + f];
        }
#pragma unroll
        for (int k = 0; k < (32 * O) / 256; k++) {
            int idx = t + k * 256;
            int o = idx % O, f = idx / O;
            ws[f][o] = Wc[(size_t)(f0 + f) * O + o];
        }
        __syncthreads();
#pragma unroll 8
        for (int f = 0; f < 32; f++) {
            float xv[TM], wv[TN];
#pragma unroll
            for (int q = 0; q < TM / 4; q++)
                *(float4*)&xv[q * 4] = *(const float4*)&xs[f][rg * TM + q * 4];
            if (TN >= 4) {
#pragma unroll
                for (int q = 0; q < TN / 4; q++)
                    *(float4*)&wv[q * 4] = *(const float4*)&ws[f][cg * TN + q * 4];
            } else {
                *(float2*)&wv[0] = *(const float2*)&ws[f][cg * TN];
            }
#pragma unroll
            for (int k = 0; k < TM; k++)
#pragma unroll
                for (int u = 0; u < TN; u++) acc[k][u] += xv[k] * wv[u];
        }
    }
#pragma unroll
    for (int k = 0; k < TM; k++) {
        int n = n0 + rg * TM + k;
#pragma unroll
        for (int u = 0; u < TN; u++)
            g_Wh[((size_t)h * Nn + n) * O + cg * TN + u] = acc[k][u];
    }
}

// ---------------- per-node attention scalars ---------------------------------
template <int O>
__global__ void fe_kernel(const float* __restrict__ a) {
    int idx = blockIdx.x * 256 + threadIdx.x;  // over Hh*Nn
    int h = idx >> 12;                          // / Nn
    const float* wr = g_Wh + (size_t)idx * O;
    const float* av = a + h * 2 * O;
    float f1 = 0.f, f2 = 0.f;
#pragma unroll
    for (int o = 0; o < O; o++) {
        float w = wr[o];
        f1 += w * av[o];
        f2 += w * av[O + o];
    }
    g_E1[idx] = make_float2(expf(f1), expf(0.2f * f1));
    g_E2[idx] = make_float2(expf(f2), expf(0.2f * f2));
}

// ---------------- tf32 tensor-core masked-softmax aggregation ----------------
// 64-row CTA tile (2 CTAs/SM), double-buffered smem, ONE barrier per chunk.
// Register pipeline: chunk c+1's weights & Wh load while chunk c's MMAs run.
template <int O>
__global__ __launch_bounds__(256) void agg_mma_kernel(float* __restrict__ out, int HO) {
    constexpr int NW_N = (O == 64) ? 4 : 2;     // warp grid cols (8 warps)
    constexpr int NW_M = 8 / NW_N;              // warp grid rows
    constexpr int WM = 64 / NW_M;               // rows per warp
    constexpr int WN = O / NW_N;                // cols per warp
    constexpr int MT = WM / 16;                 // m16 tiles per warp
    constexpr int NT = WN / 8;                  // n8 tiles per warp
    constexpr int SB = O + 8;                   // sWh stride (conflict-free)
    constexpr int NV4 = (8 * O + 255) / 256;    // float4 Wh loads per thread

    __shared__ float sW[2][64][36];             // weights [row][k], stride 36
    __shared__ float sWh[2][32][SB];            // Wh chunk [k][o]
    __shared__ float sZq[256];
    __shared__ float sZ[64];

    const int h = blockIdx.y;
    const int n0 = blockIdx.x * 64;
    const int t = threadIdx.x;
    const int lane = t & 31, wid = t >> 5;
    const int wm = wid / NW_N, wn = wid % NW_N;
    const int row0 = wm * WM, col0 = wn * WN;

    // weight-producer mapping: 4 threads per row, strided k
    const int rq = t >> 2, kq = t & 3;
    const float2 e1 = g_E1[h * Nn + n0 + rq];
    const float* WhH = g_Wh + (size_t)h * Nn * O;
    const float2* E2H = g_E2 + h * Nn;
    const uint32_t* mrow = g_mask + (size_t)(n0 + rq) * NWORDS;

    float acc[MT][NT][4];
#pragma unroll
    for (int mt = 0; mt < MT; mt++)
#pragma unroll
        for (int nt = 0; nt < NT; nt++)
#pragma unroll
            for (int q = 0; q < 4; q++) acc[mt][nt][q] = 0.f;
    float zloc = 0.f;

    float wreg[8];
    float4 whreg[NV4];
#pragma unroll
    for (int v = 0; v < NV4; v++) whreg[v] = make_float4(0.f, 0.f, 0.f, 0.f);

    auto produce = [&](int c) {
        const int j0 = c << 5;
        uint32_t m = mrow[c];
#pragma unroll
        for (int b = 0; b < 8; b++) {
            int k = kq + b * 4;
            float2 e2 = E2H[j0 + k];
            float w = ((m >> k) & 1u) ? fmaxf(e1.x * e2.x, e1.y * e2.y) : 0.f;
            uint32_t wb;
            asm("cvt.rna.tf32.f32 %0, %1;" : "=r"(wb) : "f"(w));
            wreg[b] = __uint_as_float(wb);
        }
#pragma unroll
        for (int v = 0; v < NV4; v++) {
            int i = t + v * 256;
            if (i < 8 * O) {
                int o4 = i % (O / 4), jw = i / (O / 4);
                float4 vv = *(const float4*)&WhH[(size_t)(j0 + jw) * O + o4 * 4];
                uint32_t c0, c1, c2, c3;
                asm("cvt.rna.tf32.f32 %0, %1;" : "=r"(c0) : "f"(vv.x));
                asm("cvt.rna.tf32.f32 %0, %1;" : "=r"(c1) : "f"(vv.y));
                asm("cvt.rna.tf32.f32 %0, %1;" : "=r"(c2) : "f"(vv.z));
                asm("cvt.rna.tf32.f32 %0, %1;" : "=r"(c3) : "f"(vv.w));
                whreg[v] = make_float4(__uint_as_float(c0), __uint_as_float(c1),
                                       __uint_as_float(c2), __uint_as_float(c3));
            }
        }
    };

    produce(0);

    for (int c = 0; c < NWORDS; c++) {
        const int buf = c & 1;
        // store phase: regs -> smem[buf]
#pragma unroll
        for (int b = 0; b < 8; b++) {
            sW[buf][rq][kq + b * 4] = wreg[b];
            zloc += wreg[b];
        }
#pragma unroll
        for (int v = 0; v < NV4; v++) {
            int i = t + v * 256;
            if (i < 8 * O) {
                int o4 = i % (O / 4), jw = i / (O / 4);
                *(float4*)&sWh[buf][jw][o4 * 4] = whreg[v];
            }
        }
        __syncthreads();  // single barrier: stores visible, prev buf free
        // next chunk's global loads overlap the MMAs below
        if (c + 1 < NWORDS) produce(c + 1);
        // consume: 4 k-steps of 8, mma m16n8k8 tf32
#pragma unroll
        for (int ks = 0; ks < 4; ks++) {
            const int k0 = ks * 8;
            uint32_t a[MT][4], bb[NT][2];
            const int kk = k0 + (lane & 3);
            const int rl = lane >> 2;
#pragma unroll
            for (int mt = 0; mt < MT; mt++) {
                int r = row0 + mt * 16 + rl;
                a[mt][0] = __float_as_uint(sW[buf][r][kk]);
                a[mt][1] = __float_as_uint(sW[buf][r + 8][kk]);
                a[mt][2] = __float_as_uint(sW[buf][r][kk + 4]);
                a[mt][3] = __float_as_uint(sW[buf][r + 8][kk + 4]);
            }
#pragma unroll
            for (int nt = 0; nt < NT; nt++) {
                int n = col0 + nt * 8 + rl;
                bb[nt][0] = __float_as_uint(sWh[buf][kk][n]);
                bb[nt][1] = __float_as_uint(sWh[buf][kk + 4][n]);
            }
#pragma unroll
            for (int mt = 0; mt < MT; mt++)
#pragma unroll
                for (int nt = 0; nt < NT; nt++)
                    asm volatile(
                        "mma.sync.aligned.m16n8k8.row.col.f32.tf32.tf32.f32 "
                        "{%0,%1,%2,%3}, {%4,%5,%6,%7}, {%8,%9}, {%0,%1,%2,%3};"
                        : "+f"(acc[mt][nt][0]), "+f"(acc[mt][nt][1]),
                          "+f"(acc[mt][nt][2]), "+f"(acc[mt][nt][3])
                        : "r"(a[mt][0]), "r"(a[mt][1]), "r"(a[mt][2]), "r"(a[mt][3]),
                          "r"(bb[nt][0]), "r"(bb[nt][1]));
        }
    }
    // reduce Z per row (4 producer threads per row)
    sZq[t] = zloc;
    __syncthreads();
    if (t < 64)
        sZ[t] = sZq[t * 4] + sZq[t * 4 + 1] + sZq[t * 4 + 2] + sZq[t * 4 + 3];
    __syncthreads();
    // epilogue: normalize, ELU, head-concat store
#pragma unroll
    for (int mt = 0; mt < MT; mt++) {
        int r = row0 + mt * 16 + (lane >> 2);
        float iz0 = 1.f / sZ[r];
        float iz1 = 1.f / sZ[r + 8];
#pragma unroll
        for (int nt = 0; nt < NT; nt++) {
            int cb = col0 + nt * 8 + (lane & 3) * 2;
            float v0 = acc[mt][nt][0] * iz0;
            float v1 = acc[mt][nt][1] * iz0;
            float v2 = acc[mt][nt][2] * iz1;
            float v3 = acc[mt][nt][3] * iz1;
            v0 = v0 > 0.f ? v0 : expm1f(v0);
            v1 = v1 > 0.f ? v1 : expm1f(v1);
            v2 = v2 > 0.f ? v2 : expm1f(v2);
            v3 = v3 > 0.f ? v3 : expm1f(v3);
            *(float2*)&out[(size_t)(n0 + r) * HO + h * O + cb] = make_float2(v0, v1);
            *(float2*)&out[(size_t)(n0 + r + 8) * HO + h * O + cb] = make_float2(v2, v3);
        }
    }
}

// ---------------- final linear + log_softmax ---------------------------------
__global__ void final_kernel(const float* __restrict__ Wlin,
                             const float* __restrict__ blin,
                             float* __restrict__ out) {
    int lane = threadIdx.x & 31;
    int n = (blockIdx.x * blockDim.x + threadIdx.x) >> 5;  // one warp per row
    const float* hr = g_h3 + (size_t)n * 64;
    float v1 = -INFINITY;
    float a0 = blin[lane];
    float a1v = (lane < 8) ? blin[lane + 32] : 0.f;
#pragma unroll 16
    for (int k = 0; k < 64; k++) {
        float hv = hr[k];
        a0 += hv * Wlin[k * 40 + lane];
        if (lane < 8) a1v += hv * Wlin[k * 40 + lane + 32];
    }
    float v0 = a0;
    if (lane < 8) v1 = a1v;
    float m = fmaxf(v0, v1);
#pragma unroll
    for (int off = 16; off; off >>= 1) m = fmaxf(m, __shfl_xor_sync(0xffffffffu, m, off));
    float e = expf(v0 - m) + ((lane < 8) ? expf(v1 - m) : 0.f);
#pragma unroll
    for (int off = 16; off; off >>= 1) e += __shfl_xor_sync(0xffffffffu, e, off);
    float lse = m + logf(e);
    out[(size_t)n * 40 + lane] = v0 - lse;
    if (lane < 8) out[(size_t)n * 40 + lane + 32] = v1 - lse;
}

// ---------------- launch -----------------------------------------------------
extern "C" void kernel_launch(void* const* d_in, const int* in_sizes, int n_in,
                              void* d_out, int out_size) {
    const float* x    = (const float*)d_in[0];
    const int*   adj  = (const int*)d_in[1];
    const float* W1   = (const float*)d_in[2];
    const float* a1   = (const float*)d_in[3];
    const float* W2   = (const float*)d_in[4];
    const float* a2   = (const float*)d_in[5];
    const float* W3   = (const float*)d_in[6];
    const float* a3   = (const float*)d_in[7];
    const float* Wlin = (const float*)d_in[8];
    const float* blin = (const float*)d_in[9];
    float* out = (float*)d_out;

    float *h1, *h2, *h3;
    cudaGetSymbolAddress((void**)&h1, g_h1);
    cudaGetSymbolAddress((void**)&h2, g_h2);
    cudaGetSymbolAddress((void**)&h3, g_h3);

    pack_mask_kernel<<<(Nn * NWORDS) / 256, 256>>>(adj);

    dim3 ggrid(Nn / 128, Hh);
    dim3 agrid(Nn / 64, Hh);

    // stage 1: Fin=512, O=64
    gemm_wh_kernel<512, 64, 8, 4><<<ggrid, 256>>>(x, W1);
    fe_kernel<64><<<(Hh * Nn) / 256, 256>>>(a1);
    agg_mma_kernel<64><<<agrid, 256>>>(h1, 256);

    // stage 2: Fin=256, O=32
    gemm_wh_kernel<256, 32, 4, 4><<<ggrid, 256>>>(h1, W2);
    fe_kernel<32><<<(Hh * Nn) / 256, 256>>>(a2);
    agg_mma_kernel<32><<<agrid, 256>>>(h2, 128);

    // stage 3: Fin=128, O=16
    gemm_wh_kernel<128, 16, 4, 2><<<ggrid, 256>>>(h2, W3);
    fe_kernel<16><<<(Hh * Nn) / 256, 256>>>(a3);
    agg_mma_kernel<16><<<agrid, 256>>>(h3, 64);

    final_kernel<<<(Nn * 32) / 256, 256>>>(Wlin, blin, out);
}

// round 7
// speedup vs baseline: 3.2236x; 1.2741x over previous
#include <cuda_runtime.h>
#include <cuda_fp16.h>
#include <math.h>
#include <stdint.h>

#define Nn 4096
#define Hh 4
#define NWORDS 128   // Nn/32

// ---------------- scratch (static device globals; no allocation) -------------
__device__ uint32_t g_mask[Nn * NWORDS];          // 2 MB packed adjacency
__device__ float g_Wh[Hh * Nn * 64];              // 4 MB, reused per stage (max O=64)
__device__ float2 g_E1[Hh * Nn];                  // (e^f1, e^{0.2 f1}) per node
__device__ float2 g_E2[Hh * Nn];                  // (e^f2, e^{0.2 f2}) per node
__device__ float g_h1[Nn * 256];
__device__ float g_h2[Nn * 128];
__device__ float g_h3[Nn * 64];

static __device__ __forceinline__ uint32_t smem_cast(const void* p) {
    return (uint32_t)__cvta_generic_to_shared(p);
}

static __device__ __forceinline__ void ldsm_x4(uint32_t& r0, uint32_t& r1,
                                               uint32_t& r2, uint32_t& r3,
                                               uint32_t addr) {
    asm volatile("ldmatrix.sync.aligned.m8n8.x4.shared.b16 {%0,%1,%2,%3}, [%4];"
                 : "=r"(r0), "=r"(r1), "=r"(r2), "=r"(r3) : "r"(addr));
}

static __device__ __forceinline__ void ldsm_x2t(uint32_t& r0, uint32_t& r1,
                                                uint32_t addr) {
    asm volatile("ldmatrix.sync.aligned.m8n8.x2.trans.shared.b16 {%0,%1}, [%2];"
                 : "=r"(r0), "=r"(r1) : "r"(addr));
}

// ---------------- pack adjacency into bitmask --------------------------------
__global__ void pack_mask_kernel(const int* __restrict__ adj) {
    int idx = blockIdx.x * blockDim.x + threadIdx.x;  // one thread per 32-bit word
    int i = idx >> 7;
    int w = idx & 127;
    const int4* p = reinterpret_cast<const int4*>(adj + (size_t)i * Nn + (w << 5));
    uint32_t m = 0u;
#pragma unroll
    for (int q = 0; q < 8; q++) {
        int4 v = p[q];
        if (v.x) m |= 1u << (q * 4 + 0);
        if (v.y) m |= 1u << (q * 4 + 1);
        if (v.z) m |= 1u << (q * 4 + 2);
        if (v.w) m |= 1u << (q * 4 + 3);
    }
    g_mask[idx] = m;
}

// ---------------- Wh = x @ W[h]  (per head) ----------------------------------
template <int FIN, int O, int TM, int TN>
__global__ __launch_bounds__(256) void gemm_wh_kernel(const float* __restrict__ x,
                                                      const float* __restrict__ W) {
    const int h = blockIdx.y;
    const int n0 = blockIdx.x * 128;
    const int t = threadIdx.x;
    __shared__ float xs[32][132];  // [f][row], padded, 16B-aligned rows
    __shared__ float ws[32][O];    // [f][o]
    const int CG = O / TN;
    const int rg = t / CG, cg = t % CG;
    float acc[TM][TN];
#pragma unroll
    for (int k = 0; k < TM; k++)
#pragma unroll
        for (int u = 0; u < TN; u++) acc[k][u] = 0.f;
    const float* Wc = W + (size_t)h * FIN * O;
    for (int f0 = 0; f0 < FIN; f0 += 32) {
        __syncthreads();
#pragma unroll
        for (int k = 0; k < 16; k++) {
            int idx = t + k * 256;
            int f = idx & 31, row = idx >> 5;
            xs[f][row] = x[(size_t)(n0 + row) * FIN + f0 + f];
        }
#pragma unroll
        for (int k = 0; k < (32 * O) / 256; k++) {
            int idx = t + k * 256;
            int o = idx % O, f = idx / O;
            ws[f][o] = Wc[(size_t)(f0 + f) * O + o];
        }
        __syncthreads();
#pragma unroll 8
        for (int f = 0; f < 32; f++) {
            float xv[TM], wv[TN];
#pragma unroll
            for (int q = 0; q < TM / 4; q++)
                *(float4*)&xv[q * 4] = *(const float4*)&xs[f][rg * TM + q * 4];
            if (TN >= 4) {
#pragma unroll
                for (int q = 0; q < TN / 4; q++)
                    *(float4*)&wv[q * 4] = *(const float4*)&ws[f][cg * TN + q * 4];
            } else {
                *(float2*)&wv[0] = *(const float2*)&ws[f][cg * TN];
            }
#pragma unroll
            for (int k = 0; k < TM; k++)
#pragma unroll
                for (int u = 0; u < TN; u++) acc[k][u] += xv[k] * wv[u];
        }
    }
#pragma unroll
    for (int k = 0; k < TM; k++) {
        int n = n0 + rg * TM + k;
#pragma unroll
        for (int u = 0; u < TN; u++)
            g_Wh[((size_t)h * Nn + n) * O + cg * TN + u] = acc[k][u];
    }
}

// ---------------- per-node attention scalars ---------------------------------
template <int O>
__global__ void fe_kernel(const float* __restrict__ a) {
    int idx = blockIdx.x * 256 + threadIdx.x;  // over Hh*Nn
    int h = idx >> 12;                          // / Nn
    const float* wr = g_Wh + (size_t)idx * O;
    const float* av = a + h * 2 * O;
    float f1 = 0.f, f2 = 0.f;
#pragma unroll
    for (int o = 0; o < O; o++) {
        float w = wr[o];
        f1 += w * av[o];
        f2 += w * av[O + o];
    }
    g_E1[idx] = make_float2(expf(f1), expf(0.2f * f1));
    g_E2[idx] = make_float2(expf(f2), expf(0.2f * f2));
}

// ---------------- fp16 tensor-core masked-softmax aggregation ----------------
// w_ij = exp(leaky(f1_i+f2_j)) = max(e^f1*e^f2, e^{0.2f1}*e^{0.2f2}), fp16.
// 64-row CTA tile, double-buffered smem, ONE barrier per chunk, register
// pipeline; fragments via ldmatrix, mma m16n8k16 f16 with fp32 accum.
template <int O>
__global__ __launch_bounds__(256) void agg_mma_kernel(float* __restrict__ out, int HO) {
    constexpr int NW_N = (O == 64) ? 4 : 2;     // warp grid cols (8 warps)
    constexpr int NW_M = 8 / NW_N;              // warp grid rows
    constexpr int WM = 64 / NW_M;               // rows per warp
    constexpr int WN = O / NW_N;                // cols per warp
    constexpr int MT = WM / 16;                 // m16 tiles per warp
    constexpr int NT = WN / 8;                  // n8 tiles per warp
    constexpr int SWS = 40;                     // sW stride (halves), 80B rows
    constexpr int SBS = O + 8;                  // sWh stride (halves)
    constexpr int NV4 = (8 * O + 255) / 256;    // float4 Wh loads per thread

    __shared__ __align__(16) __half sW[2][64][SWS];   // weights [row][k]
    __shared__ __align__(16) __half sWh[2][32][SBS];  // Wh chunk [k][o]
    __shared__ float sZq[256];
    __shared__ float sZ[64];

    const int h = blockIdx.y;
    const int n0 = blockIdx.x * 64;
    const int t = threadIdx.x;
    const int lane = t & 31, wid = t >> 5;
    const int wm = wid / NW_N, wn = wid % NW_N;
    const int row0 = wm * WM, col0 = wn * WN;

    // weight-producer mapping: 4 threads per row, contiguous 8-k segments
    const int rq = t >> 2, kq = t & 3;
    const float2 e1 = g_E1[h * Nn + n0 + rq];
    const float* WhH = g_Wh + (size_t)h * Nn * O;
    const float2* E2H = g_E2 + h * Nn;
    const uint32_t* mrow = g_mask + (size_t)(n0 + rq) * NWORDS;

    float acc[MT][NT][4];
#pragma unroll
    for (int mt = 0; mt < MT; mt++)
#pragma unroll
        for (int nt = 0; nt < NT; nt++)
#pragma unroll
            for (int q = 0; q < 4; q++) acc[mt][nt][q] = 0.f;
    float zloc = 0.f;

    uint32_t wreg[4];       // 8 halves (k = kq*8 .. kq*8+7)
    float4 whreg[NV4];
#pragma unroll
    for (int v = 0; v < NV4; v++) whreg[v] = make_float4(0.f, 0.f, 0.f, 0.f);

    auto produce = [&](int c) {
        const int j0 = c << 5;
        uint32_t m = mrow[c] >> (kq * 8);
#pragma unroll
        for (int b = 0; b < 8; b += 2) {
            float2 e2a = E2H[j0 + kq * 8 + b];
            float2 e2b = E2H[j0 + kq * 8 + b + 1];
            float wa = ((m >> b) & 1u) ? fmaxf(e1.x * e2a.x, e1.y * e2a.y) : 0.f;
            float wb = ((m >> (b + 1)) & 1u) ? fmaxf(e1.x * e2b.x, e1.y * e2b.y) : 0.f;
            __half2 hw = __floats2half2_rn(wa, wb);
            wreg[b >> 1] = *(uint32_t*)&hw;
        }
#pragma unroll
        for (int v = 0; v < NV4; v++) {
            int i = t + v * 256;
            if (i < 8 * O)
                whreg[v] = *(const float4*)&WhH[(size_t)(j0 + i / (O / 4)) * O +
                                                (i % (O / 4)) * 4];
        }
    };

    produce(0);

    for (int c = 0; c < NWORDS; c++) {
        const int buf = c & 1;
        // store phase: regs -> smem[buf], accumulate Z from fp16-rounded w
#pragma unroll
        for (int i = 0; i < 4; i++) {
            *(uint32_t*)&sW[buf][rq][kq * 8 + i * 2] = wreg[i];
            float2 f = __half22float2(*(__half2*)&wreg[i]);
            zloc += f.x + f.y;
        }
#pragma unroll
        for (int v = 0; v < NV4; v++) {
            int i = t + v * 256;
            if (i < 8 * O) {
                __half2 lo = __floats2half2_rn(whreg[v].x, whreg[v].y);
                __half2 hi = __floats2half2_rn(whreg[v].z, whreg[v].w);
                uint2 pk = make_uint2(*(uint32_t*)&lo, *(uint32_t*)&hi);
                *(uint2*)&sWh[buf][i / (O / 4)][(i % (O / 4)) * 4] = pk;
            }
        }
        __syncthreads();  // single barrier: stores visible, prev buf free
        // next chunk's global loads overlap the MMAs below
        if (c + 1 < NWORDS) produce(c + 1);
        // consume: 2 k-steps of 16, mma m16n8k16 f16, ldmatrix fragments
#pragma unroll
        for (int ks = 0; ks < 2; ks++) {
            uint32_t a[MT][4], bb[NT][2];
            uint32_t abase = smem_cast(
                &sW[buf][row0 + (lane & 15)][ks * 16 + ((lane >> 4) & 1) * 8]);
            uint32_t bbase = smem_cast(&sWh[buf][ks * 16 + (lane & 15)][col0]);
#pragma unroll
            for (int mt = 0; mt < MT; mt++)
                ldsm_x4(a[mt][0], a[mt][1], a[mt][2], a[mt][3],
                        abase + mt * 16 * SWS * 2);
#pragma unroll
            for (int nt = 0; nt < NT; nt++)
                ldsm_x2t(bb[nt][0], bb[nt][1], bbase + nt * 16);
#pragma unroll
            for (int mt = 0; mt < MT; mt++)
#pragma unroll
                for (int nt = 0; nt < NT; nt++)
                    asm volatile(
                        "mma.sync.aligned.m16n8k16.row.col.f32.f16.f16.f32 "
                        "{%0,%1,%2,%3}, {%4,%5,%6,%7}, {%8,%9}, {%0,%1,%2,%3};"
                        : "+f"(acc[mt][nt][0]), "+f"(acc[mt][nt][1]),
                          "+f"(acc[mt][nt][2]), "+f"(acc[mt][nt][3])
                        : "r"(a[mt][0]), "r"(a[mt][1]), "r"(a[mt][2]), "r"(a[mt][3]),
                          "r"(bb[nt][0]), "r"(bb[nt][1]));
        }
    }
    // reduce Z per row (4 producer threads per row)
    sZq[t] = zloc;
    __syncthreads();
    if (t < 64)
        sZ[t] = sZq[t * 4] + sZq[t * 4 + 1] + sZq[t * 4 + 2] + sZq[t * 4 + 3];
    __syncthreads();
    // epilogue: normalize, ELU, head-concat store
#pragma unroll
    for (int mt = 0; mt < MT; mt++) {
        int r = row0 + mt * 16 + (lane >> 2);
        float iz0 = 1.f / sZ[r];
        float iz1 = 1.f / sZ[r + 8];
#pragma unroll
        for (int nt = 0; nt < NT; nt++) {
            int cb = col0 + nt * 8 + (lane & 3) * 2;
            float v0 = acc[mt][nt][0] * iz0;
            float v1 = acc[mt][nt][1] * iz0;
            float v2 = acc[mt][nt][2] * iz1;
            float v3 = acc[mt][nt][3] * iz1;
            v0 = v0 > 0.f ? v0 : expm1f(v0);
            v1 = v1 > 0.f ? v1 : expm1f(v1);
            v2 = v2 > 0.f ? v2 : expm1f(v2);
            v3 = v3 > 0.f ? v3 : expm1f(v3);
            *(float2*)&out[(size_t)(n0 + r) * HO + h * O + cb] = make_float2(v0, v1);
            *(float2*)&out[(size_t)(n0 + r + 8) * HO + h * O + cb] = make_float2(v2, v3);
        }
    }
}

// ---------------- final linear + log_softmax ---------------------------------
__global__ void final_kernel(const float* __restrict__ Wlin,
                             const float* __restrict__ blin,
                             float* __restrict__ out) {
    int lane = threadIdx.x & 31;
    int n = (blockIdx.x * blockDim.x + threadIdx.x) >> 5;  // one warp per row
    const float* hr = g_h3 + (size_t)n * 64;
    float v1 = -INFINITY;
    float a0 = blin[lane];
    float a1v = (lane < 8) ? blin[lane + 32] : 0.f;
#pragma unroll 16
    for (int k = 0; k < 64; k++) {
        float hv = hr[k];
        a0 += hv * Wlin[k * 40 + lane];
        if (lane < 8) a1v += hv * Wlin[k * 40 + lane + 32];
    }
    float v0 = a0;
    if (lane < 8) v1 = a1v;
    float m = fmaxf(v0, v1);
#pragma unroll
    for (int off = 16; off; off >>= 1) m = fmaxf(m, __shfl_xor_sync(0xffffffffu, m, off));
    float e = expf(v0 - m) + ((lane < 8) ? expf(v1 - m) : 0.f);
#pragma unroll
    for (int off = 16; off; off >>= 1) e += __shfl_xor_sync(0xffffffffu, e, off);
    float lse = m + logf(e);
    out[(size_t)n * 40 + lane] = v0 - lse;
    if (lane < 8) out[(size_t)n * 40 + lane + 32] = v1 - lse;
}

// ---------------- launch -----------------------------------------------------
extern "C" void kernel_launch(void* const* d_in, const int* in_sizes, int n_in,
                              void* d_out, int out_size) {
    const float* x    = (const float*)d_in[0];
    const int*   adj  = (const int*)d_in[1];
    const float* W1   = (const float*)d_in[2];
    const float* a1   = (const float*)d_in[3];
    const float* W2   = (const float*)d_in[4];
    const float* a2   = (const float*)d_in[5];
    const float* W3   = (const float*)d_in[6];
    const float* a3   = (const float*)d_in[7];
    const float* Wlin = (const float*)d_in[8];
    const float* blin = (const float*)d_in[9];
    float* out = (float*)d_out;

    float *h1, *h2, *h3;
    cudaGetSymbolAddress((void**)&h1, g_h1);
    cudaGetSymbolAddress((void**)&h2, g_h2);
    cudaGetSymbolAddress((void**)&h3, g_h3);

    pack_mask_kernel<<<(Nn * NWORDS) / 256, 256>>>(adj);

    dim3 ggrid(Nn / 128, Hh);
    dim3 agrid(Nn / 64, Hh);

    // stage 1: Fin=512, O=64
    gemm_wh_kernel<512, 64, 8, 4><<<ggrid, 256>>>(x, W1);
    fe_kernel<64><<<(Hh * Nn) / 256, 256>>>(a1);
    agg_mma_kernel<64><<<agrid, 256>>>(h1, 256);

    // stage 2: Fin=256, O=32
    gemm_wh_kernel<256, 32, 4, 4><<<ggrid, 256>>>(h1, W2);
    fe_kernel<32><<<(Hh * Nn) / 256, 256>>>(a2);
    agg_mma_kernel<32><<<agrid, 256>>>(h2, 128);

    // stage 3: Fin=128, O=16
    gemm_wh_kernel<128, 16, 4, 2><<<ggrid, 256>>>(h2, W3);
    fe_kernel<16><<<(Hh * Nn) / 256, 256>>>(a3);
    agg_mma_kernel<16><<<agrid, 256>>>(h3, 64);

    final_kernel<<<(Nn * 32) / 256, 256>>>(Wlin, blin, out);
}